// round 12
// baseline (speedup 1.0000x reference)
#include <cuda_runtime.h>
#include <cuda_bf16.h>
#include <cstdint>

#define N_DIM 4096
#define D_DIM 256
#define TILE  128
#define GRID_TILES (N_DIM / TILE)       // 32
#define NUM_CTAS   272                  // sum_{i=0..15} (32 - 2i)

// ---------------- device scratch ----------------
__device__ __nv_bfloat16 g_xb[N_DIM * D_DIM];     // 2 MB bf16 copy of x
__device__ float g_sq[N_DIM];                      // row squared norms
__device__ float g_svec_partial[1024][D_DIM];      // colsum partials (1 MB)
__device__ float g_inv;                            // 1 / (2 * sigma^2)

// ---------------- helpers ----------------
__device__ __forceinline__ uint32_t smem_to_u32(const void* p) {
    uint32_t a;
    asm("{ .reg .u64 t; cvta.to.shared.u64 t, %1; cvt.u32.u64 %0, t; }" : "=r"(a) : "l"(p));
    return a;
}

__device__ __forceinline__ void ldsm_x4(uint32_t r[4], uint32_t addr) {
    asm volatile("ldmatrix.sync.aligned.m8n8.x4.shared.b16 {%0,%1,%2,%3}, [%4];"
                 : "=r"(r[0]), "=r"(r[1]), "=r"(r[2]), "=r"(r[3]) : "r"(addr));
}

__device__ __forceinline__ void mma_16816_bf16(float c[4], const uint32_t a[4],
                                               uint32_t b0, uint32_t b1) {
    asm volatile(
        "mma.sync.aligned.m16n8k16.row.col.f32.bf16.bf16.f32 "
        "{%0,%1,%2,%3}, {%4,%5,%6,%7}, {%8,%9}, {%0,%1,%2,%3};"
        : "+f"(c[0]), "+f"(c[1]), "+f"(c[2]), "+f"(c[3])
        : "r"(a[0]), "r"(a[1]), "r"(a[2]), "r"(a[3]), "r"(b0), "r"(b1));
}

#define CP_ASYNC_16(dst, src) \
    asm volatile("cp.async.cg.shared.global [%0], [%1], 16;" :: "r"(dst), "l"(src))
#define CP_ASYNC_COMMIT() asm volatile("cp.async.commit_group;" ::: "memory")
#define CP_ASYNC_WAIT(n)  asm volatile("cp.async.wait_group %0;" :: "n"(n) : "memory")

// ---------------- kernel 1: bf16 convert + row norms + colsum partials --------
// 1024 blocks x 256 threads; block handles 4 rows. One float4 per thread.
__global__ void prep_kernel(const float* __restrict__ x) {
    __shared__ float sh_half[8];           // per-warp (half-row) sums
    const int tid  = threadIdx.x;
    const int lane = tid & 31;
    const int r    = tid >> 6;             // local row 0..3
    const int c    = tid & 63;             // float4 index within row
    const int row  = blockIdx.x * 4 + r;

    {
        float4 v = reinterpret_cast<const float4*>(x)[(size_t)row * 64 + c];
        float s = v.x * v.x + v.y * v.y + v.z * v.z + v.w * v.w;
        __nv_bfloat162 lo = __float22bfloat162_rn(make_float2(v.x, v.y));
        __nv_bfloat162 hi = __float22bfloat162_rn(make_float2(v.z, v.w));
        reinterpret_cast<uint2*>(g_xb)[(size_t)row * 64 + c] =
            make_uint2(*reinterpret_cast<uint32_t*>(&lo),
                       *reinterpret_cast<uint32_t*>(&hi));
        #pragma unroll
        for (int o = 16; o; o >>= 1) s += __shfl_xor_sync(0xffffffffu, s, o);
        if (lane == 0) sh_half[tid >> 5] = s;
    }
    // colsum partial over this block's 4 rows (thread t = column t)
    {
        const float* base = x + (size_t)blockIdx.x * 4 * D_DIM + tid;
        float acc = base[0] + base[D_DIM] + base[2 * D_DIM] + base[3 * D_DIM];
        g_svec_partial[blockIdx.x][tid] = acc;
    }
    __syncthreads();
    if (tid < 4) g_sq[blockIdx.x * 4 + tid] = sh_half[2 * tid] + sh_half[2 * tid + 1];
}

// ---------------- kernel 2: sigma -> g_inv ----------------
__global__ void sigma_kernel() {
    const int t   = threadIdx.x;      // 1024 threads
    const int col = t & 255;
    const int grp = t >> 8;           // 4 groups of 256 partial-rows

    float scp = 0.f;
    #pragma unroll 8
    for (int b = grp * 256; b < grp * 256 + 256; b++) scp += g_svec_partial[b][col];

    __shared__ float sh_sc[4][256];
    sh_sc[grp][col] = scp;

    double sq = 0.0;
    #pragma unroll
    for (int k = 0; k < 4; k++) sq += (double)g_sq[t + k * 1024];

    __shared__ double sh[1024];
    sh[t] = sq;
    __syncthreads();

    __shared__ double sh_ss[256];
    if (t < 256) {
        double sc = (double)sh_sc[0][t] + (double)sh_sc[1][t]
                  + (double)sh_sc[2][t] + (double)sh_sc[3][t];
        sh_ss[t] = sc * sc;
    }
    __syncthreads();

    for (int o = 512; o; o >>= 1) {
        if (t < o) sh[t] += sh[t + o];
        if (o <= 128 && t < o) sh_ss[t] += sh_ss[t + o];
        __syncthreads();
    }
    if (t == 0) {
        const double N = (double)N_DIM;
        double mean_d2 = 2.0 * sh[0] / N - 2.0 * sh_ss[0] / (N * N);
        g_inv = (float)(1.0 / (2.0 * mean_d2));  // ALPHA = 1
    }
}

// ---------------- kernel 3: fused symmetric GEMM + d2 + exp -------------------
// CTA tile 256x128, 512 threads, 4x4 warps (warp tile 64x32). K in 4 chunks of
// 64; 4-stage cp.async pipeline (one buffer per chunk, 2-deep prefetch, no
// buffer reuse -> no WAR hazard). Inner loop is the proven R8 form.
#define NTHREADS   512
#define CHUNK_K    64
#define NCHUNK     (D_DIM / CHUNK_K)     // 4
#define NSTAGE     4
#define CROW_BYTES 144
#define A_ROWS     256
#define B_ROWS     128
#define SA_BYTES   (A_ROWS * CROW_BYTES)          // 36864
#define SB_BYTES   (B_ROWS * CROW_BYTES)          // 18432
#define STAGE_BYTES (SA_BYTES + SB_BYTES)         // 55296
#define GEMM_SMEM  (NSTAGE * STAGE_BYTES)         // 221184
#define T_ST 132

__global__ __launch_bounds__(NTHREADS, 1)
void gemm_fused_kernel(float* __restrict__ d_out) {
    extern __shared__ char smem[];
    const uint32_t smem_u = smem_to_u32(smem);

    const int tid  = threadIdx.x;
    const int wid  = tid >> 5;
    const int lane = tid & 31;

    // decode (strip si, col tile j): strip si has 32-2*si tiles, j = 2*si + b
    int b = blockIdx.x, si = 0, rem = 32;
    while (b >= rem) { b -= rem; rem -= 2; si++; }
    const int j = 2 * si + b;
    const int row0 = si * 256;
    const int col0 = j * TILE;
    const bool mirror = (j >= 2 * si + 2);

    const __nv_bfloat16* gA = g_xb + (size_t)row0 * D_DIM;
    const __nv_bfloat16* gB = g_xb + (size_t)col0 * D_DIM;

    auto load_chunk = [&](int c, int stage) {
        const uint32_t sA = smem_u + stage * STAGE_BYTES;
        const uint32_t sB = sA + SA_BYTES;
        #pragma unroll
        for (int it = 0; it < 4; it++) {
            int idx = tid + it * NTHREADS;
            int r = idx >> 3, q = idx & 7;
            CP_ASYNC_16(sA + (uint32_t)r * CROW_BYTES + (uint32_t)q * 16,
                        gA + (size_t)r * D_DIM + c * CHUNK_K + q * 8);
        }
        #pragma unroll
        for (int it = 0; it < 2; it++) {
            int idx = tid + it * NTHREADS;
            int r = idx >> 3, q = idx & 7;
            CP_ASYNC_16(sB + (uint32_t)r * CROW_BYTES + (uint32_t)q * 16,
                        gB + (size_t)r * D_DIM + c * CHUNK_K + q * 8);
        }
        CP_ASYNC_COMMIT();
    };

    const int warp_m = wid & 3;
    const int warp_n = wid >> 2;
    const int m0 = warp_m * 64;
    const int n0 = warp_n * 32;

    float acc[4][4][4];
    #pragma unroll
    for (int mi = 0; mi < 4; mi++)
        #pragma unroll
        for (int ni = 0; ni < 4; ni++)
            #pragma unroll
            for (int q = 0; q < 4; q++) acc[mi][ni][q] = 0.f;

    const uint32_t a_row = (uint32_t)(lane & 15);
    const uint32_t a_kof = (uint32_t)((lane >> 4) << 3);
    const uint32_t b_row = (uint32_t)(((lane >> 4) << 3) + (lane & 7));
    const uint32_t b_kof = (uint32_t)(((lane >> 3) & 1) << 3);

    // 2-deep prefetch prologue
    load_chunk(0, 0);
    load_chunk(1, 1);

    #pragma unroll
    for (int c = 0; c < NCHUNK; c++) {
        if (c + 2 < NCHUNK) load_chunk(c + 2, c + 2);
        // require chunk c complete; allow the later chunks to stay in flight
        if (c == 0)      { CP_ASYNC_WAIT(2); }
        else if (c == 1) { CP_ASYNC_WAIT(2); }
        else if (c == 2) { CP_ASYNC_WAIT(1); }
        else             { CP_ASYNC_WAIT(0); }
        __syncthreads();

        const uint32_t As_u = smem_u + c * STAGE_BYTES;
        const uint32_t Bs_u = As_u + SA_BYTES;

        #pragma unroll
        for (int ks = 0; ks < CHUNK_K / 16; ks++) {
            const uint32_t kbase = (uint32_t)ks * 32;
            uint32_t bbf[2][4];
            #pragma unroll
            for (int nb = 0; nb < 2; nb++) {
                uint32_t addr = Bs_u + (n0 + nb * 16 + b_row) * CROW_BYTES + kbase + b_kof * 2;
                ldsm_x4(bbf[nb], addr);
            }
            #pragma unroll
            for (int mi = 0; mi < 4; mi++) {
                uint32_t aa[4];
                uint32_t addr = As_u + (m0 + mi * 16 + a_row) * CROW_BYTES + kbase + a_kof * 2;
                ldsm_x4(aa, addr);
                #pragma unroll
                for (int ni = 0; ni < 4; ni++) {
                    int nb = ni >> 1, hi = ni & 1;
                    mma_16816_bf16(acc[mi][ni], aa, bbf[nb][hi * 2], bbf[nb][hi * 2 + 1]);
                }
            }
        }
    }
    __syncthreads();   // all MMAs done before smem is reused as transpose buffer

    // ---- epilogue: e = exp(-(sqi+sqj-2g)/2s^2); direct store; keep e in acc --
    const float inv = g_inv;
    #pragma unroll
    for (int mi = 0; mi < 4; mi++) {
        const int rl0 = m0 + mi * 16 + (lane >> 2);
        const int gi  = row0 + rl0;
        const float sqi0 = g_sq[gi];
        const float sqi8 = g_sq[gi + 8];
        #pragma unroll
        for (int ni = 0; ni < 4; ni++) {
            const int cl = n0 + ni * 8 + ((lane & 3) << 1);
            const int gj = col0 + cl;
            const float2 sj = *reinterpret_cast<const float2*>(&g_sq[gj]);
            float e0 = __expf(-fmaxf(sqi0 + sj.x - 2.f * acc[mi][ni][0], 0.f) * inv);
            float e1 = __expf(-fmaxf(sqi0 + sj.y - 2.f * acc[mi][ni][1], 0.f) * inv);
            float e2 = __expf(-fmaxf(sqi8 + sj.x - 2.f * acc[mi][ni][2], 0.f) * inv);
            float e3 = __expf(-fmaxf(sqi8 + sj.y - 2.f * acc[mi][ni][3], 0.f) * inv);
            *reinterpret_cast<float2*>(&d_out[(size_t)gi * N_DIM + gj])       = make_float2(e0, e1);
            *reinterpret_cast<float2*>(&d_out[(size_t)(gi + 8) * N_DIM + gj]) = make_float2(e2, e3);
            acc[mi][ni][0] = e0; acc[mi][ni][1] = e1;
            acc[mi][ni][2] = e2; acc[mi][ni][3] = e3;
        }
    }

    // ---- mirror store in two 128-row phases through smem transpose buffer ----
    if (mirror) {
        float* trans = reinterpret_cast<float*>(smem);
        #pragma unroll
        for (int p = 0; p < 2; p++) {
            if ((warp_m >> 1) == p) {
                const int rh_base = (warp_m & 1) * 64 + (lane >> 2);
                #pragma unroll
                for (int mi = 0; mi < 4; mi++) {
                    const int rh = rh_base + mi * 16;
                    #pragma unroll
                    for (int ni = 0; ni < 4; ni++) {
                        const int cl = n0 + ni * 8 + ((lane & 3) << 1);
                        trans[(cl)     * T_ST + rh]     = acc[mi][ni][0];
                        trans[(cl + 1) * T_ST + rh]     = acc[mi][ni][1];
                        trans[(cl)     * T_ST + rh + 8] = acc[mi][ni][2];
                        trans[(cl + 1) * T_ST + rh + 8] = acc[mi][ni][3];
                    }
                }
            }
            __syncthreads();
            #pragma unroll
            for (int it = 0; it < 8; it++) {
                int e4 = tid + it * NTHREADS;
                int r  = e4 >> 5;
                int c4 = e4 & 31;
                const float* src = &trans[r * T_ST + c4 * 4];
                float4 v = make_float4(src[0], src[1], src[2], src[3]);
                *reinterpret_cast<float4*>(
                    &d_out[(size_t)(col0 + r) * N_DIM + row0 + p * 128 + c4 * 4]) = v;
            }
            __syncthreads();
        }
    }
}

// ---------------- launcher ----------------
extern "C" void kernel_launch(void* const* d_in, const int* in_sizes, int n_in,
                              void* d_out, int out_size) {
    const float* x = (const float*)d_in[0];
    float* out = (float*)d_out;

    static bool attr_set = false;
    if (!attr_set) {
        cudaFuncSetAttribute(gemm_fused_kernel,
                             cudaFuncAttributeMaxDynamicSharedMemorySize, GEMM_SMEM);
        attr_set = true;
    }

    prep_kernel<<<1024, 256>>>(x);
    sigma_kernel<<<1, 1024>>>();
    gemm_fused_kernel<<<NUM_CTAS, NTHREADS, GEMM_SMEM>>>(out);
}

// round 14
// speedup vs baseline: 1.2023x; 1.2023x over previous
#include <cuda_runtime.h>
#include <cuda_bf16.h>
#include <cstdint>

#define N_DIM 4096
#define D_DIM 256
#define TILE  128
#define GRID_TILES (N_DIM / TILE)       // 32
#define NUM_CTAS   272                  // sum_{i=0..15} (32 - 2i)

// ---------------- device scratch ----------------
__device__ __nv_bfloat16 g_xb[N_DIM * D_DIM];     // 2 MB bf16 copy of x
__device__ float g_sq[N_DIM];                      // row squared norms
__device__ float g_svec_partial[1024][D_DIM];      // colsum partials (1 MB)
__device__ float g_svec2[64][D_DIM];               // stage-2 colsum partials
__device__ float g_sqp[64];                        // stage-2 row-norm partials
__device__ float g_inv;                            // 1 / (2 * sigma^2)

// ---------------- helpers ----------------
__device__ __forceinline__ uint32_t smem_to_u32(const void* p) {
    uint32_t a;
    asm("{ .reg .u64 t; cvta.to.shared.u64 t, %1; cvt.u32.u64 %0, t; }" : "=r"(a) : "l"(p));
    return a;
}

__device__ __forceinline__ void ldsm_x4(uint32_t r[4], uint32_t addr) {
    asm volatile("ldmatrix.sync.aligned.m8n8.x4.shared.b16 {%0,%1,%2,%3}, [%4];"
                 : "=r"(r[0]), "=r"(r[1]), "=r"(r[2]), "=r"(r[3]) : "r"(addr));
}

__device__ __forceinline__ void mma_16816_bf16(float c[4], const uint32_t a[4],
                                               uint32_t b0, uint32_t b1) {
    asm volatile(
        "mma.sync.aligned.m16n8k16.row.col.f32.bf16.bf16.f32 "
        "{%0,%1,%2,%3}, {%4,%5,%6,%7}, {%8,%9}, {%0,%1,%2,%3};"
        : "+f"(c[0]), "+f"(c[1]), "+f"(c[2]), "+f"(c[3])
        : "r"(a[0]), "r"(a[1]), "r"(a[2]), "r"(a[3]), "r"(b0), "r"(b1));
}

#define CP_ASYNC_16(dst, src) \
    asm volatile("cp.async.cg.shared.global [%0], [%1], 16;" :: "r"(dst), "l"(src))
#define CP_ASYNC_COMMIT() asm volatile("cp.async.commit_group;" ::: "memory")
#define CP_ASYNC_WAIT(n)  asm volatile("cp.async.wait_group %0;" :: "n"(n) : "memory")

// ---------------- kernel 1: bf16 convert + row norms + colsum partials --------
// 1024 blocks x 256 threads; block handles 4 rows (measured 4.77 us).
__global__ void prep_kernel(const float* __restrict__ x) {
    __shared__ float sh_half[8];
    const int tid  = threadIdx.x;
    const int lane = tid & 31;
    const int r    = tid >> 6;             // local row 0..3
    const int c    = tid & 63;             // float4 index within row
    const int row  = blockIdx.x * 4 + r;

    {
        float4 v = reinterpret_cast<const float4*>(x)[(size_t)row * 64 + c];
        float s = v.x * v.x + v.y * v.y + v.z * v.z + v.w * v.w;
        __nv_bfloat162 lo = __float22bfloat162_rn(make_float2(v.x, v.y));
        __nv_bfloat162 hi = __float22bfloat162_rn(make_float2(v.z, v.w));
        reinterpret_cast<uint2*>(g_xb)[(size_t)row * 64 + c] =
            make_uint2(*reinterpret_cast<uint32_t*>(&lo),
                       *reinterpret_cast<uint32_t*>(&hi));
        #pragma unroll
        for (int o = 16; o; o >>= 1) s += __shfl_xor_sync(0xffffffffu, s, o);
        if (lane == 0) sh_half[tid >> 5] = s;
    }
    {
        const float* base = x + (size_t)blockIdx.x * 4 * D_DIM + tid;
        float acc = base[0] + base[D_DIM] + base[2 * D_DIM] + base[3 * D_DIM];
        g_svec_partial[blockIdx.x][tid] = acc;
    }
    __syncthreads();
    if (tid < 4) g_sq[blockIdx.x * 4 + tid] = sh_half[2 * tid] + sh_half[2 * tid + 1];
}

// ---------------- kernel 2a: parallel fold 1024 -> 64 partial rows ------------
__global__ void sigma_a_kernel() {
    const int b = blockIdx.x;    // 64 blocks
    const int t = threadIdx.x;   // 256 threads
    float s = 0.f;
    #pragma unroll
    for (int r = 0; r < 16; r++) s += g_svec_partial[b * 16 + r][t];
    g_svec2[b][t] = s;

    // fold 64 row-norms into one partial (deterministic fixed order)
    __shared__ float sh[64];
    if (t < 64) sh[t] = g_sq[b * 64 + t];
    __syncthreads();
    if (t < 32) {
        float v = sh[t] + sh[t + 32];
        #pragma unroll
        for (int o = 16; o; o >>= 1) v += __shfl_xor_sync(0xffffffffu, v, o);
        if (t == 0) g_sqp[b] = v;
    }
}

// ---------------- kernel 2b: final sigma -> g_inv (reads only 64.25 KB) -------
__global__ void sigma_b_kernel() {
    const int t = threadIdx.x;   // 256 threads
    float sc = 0.f;
    #pragma unroll
    for (int r = 0; r < 64; r++) sc += g_svec2[r][t];   // coalesced
    __shared__ double sh_ss[256], sh_sq[256];
    sh_ss[t] = (double)sc * (double)sc;
    sh_sq[t] = (t < 64) ? (double)g_sqp[t] : 0.0;
    __syncthreads();
    for (int o = 128; o; o >>= 1) {
        if (t < o) { sh_ss[t] += sh_ss[t + o]; sh_sq[t] += sh_sq[t + o]; }
        __syncthreads();
    }
    if (t == 0) {
        const double N = (double)N_DIM;
        double mean_d2 = 2.0 * sh_sq[0] / N - 2.0 * sh_ss[0] / (N * N);
        g_inv = (float)(1.0 / (2.0 * mean_d2));  // ALPHA = 1
    }
}

// ---------------- kernel 3: fused symmetric GEMM + d2 + exp -------------------
// EXACT 41.0-us configuration: CTA tile 256x128, 512 threads, 4x4 warps (warp
// tile 64x32), K in 4 chunks of 64, 3-stage cp.async pipeline, one sync per
// chunk, plain (compiler-scheduled) inner loop.
#define NTHREADS   512
#define CHUNK_K    64
#define NCHUNK     (D_DIM / CHUNK_K)     // 4
#define NSTAGE     3
#define CROW_BYTES 144
#define A_ROWS     256
#define B_ROWS     128
#define SA_BYTES   (A_ROWS * CROW_BYTES)          // 36864
#define SB_BYTES   (B_ROWS * CROW_BYTES)          // 18432
#define STAGE_BYTES (SA_BYTES + SB_BYTES)         // 55296
#define GEMM_SMEM  (NSTAGE * STAGE_BYTES)         // 165888
#define T_ST 132

__global__ __launch_bounds__(NTHREADS, 1)
void gemm_fused_kernel(float* __restrict__ d_out) {
    extern __shared__ char smem[];
    const uint32_t smem_u = smem_to_u32(smem);

    const int tid  = threadIdx.x;
    const int wid  = tid >> 5;
    const int lane = tid & 31;

    // decode (strip si, col tile j): strip si has 32-2*si tiles, j = 2*si + b
    int b = blockIdx.x, si = 0, rem = 32;
    while (b >= rem) { b -= rem; rem -= 2; si++; }
    const int j = 2 * si + b;
    const int row0 = si * 256;
    const int col0 = j * TILE;
    const bool mirror = (j >= 2 * si + 2);

    const __nv_bfloat16* gA = g_xb + (size_t)row0 * D_DIM;
    const __nv_bfloat16* gB = g_xb + (size_t)col0 * D_DIM;

    auto load_chunk = [&](int c, int stage) {
        const uint32_t sA = smem_u + stage * STAGE_BYTES;
        const uint32_t sB = sA + SA_BYTES;
        #pragma unroll
        for (int it = 0; it < 4; it++) {
            int idx = tid + it * NTHREADS;
            int r = idx >> 3, q = idx & 7;
            CP_ASYNC_16(sA + (uint32_t)r * CROW_BYTES + (uint32_t)q * 16,
                        gA + (size_t)r * D_DIM + c * CHUNK_K + q * 8);
        }
        #pragma unroll
        for (int it = 0; it < 2; it++) {
            int idx = tid + it * NTHREADS;
            int r = idx >> 3, q = idx & 7;
            CP_ASYNC_16(sB + (uint32_t)r * CROW_BYTES + (uint32_t)q * 16,
                        gB + (size_t)r * D_DIM + c * CHUNK_K + q * 8);
        }
        CP_ASYNC_COMMIT();
    };

    const int warp_m = wid & 3;
    const int warp_n = wid >> 2;
    const int m0 = warp_m * 64;
    const int n0 = warp_n * 32;

    float acc[4][4][4];
    #pragma unroll
    for (int mi = 0; mi < 4; mi++)
        #pragma unroll
        for (int ni = 0; ni < 4; ni++)
            #pragma unroll
            for (int q = 0; q < 4; q++) acc[mi][ni][q] = 0.f;

    const uint32_t a_row = (uint32_t)(lane & 15);
    const uint32_t a_kof = (uint32_t)((lane >> 4) << 3);
    const uint32_t b_row = (uint32_t)(((lane >> 4) << 3) + (lane & 7));
    const uint32_t b_kof = (uint32_t)(((lane >> 3) & 1) << 3);

    load_chunk(0, 0);

    #pragma unroll
    for (int c = 0; c < NCHUNK; c++) {
        const int stage = c % NSTAGE;
        if (c + 1 < NCHUNK) { load_chunk(c + 1, (c + 1) % NSTAGE); CP_ASYNC_WAIT(1); }
        else                { CP_ASYNC_WAIT(0); }
        __syncthreads();

        const uint32_t As_u = smem_u + stage * STAGE_BYTES;
        const uint32_t Bs_u = As_u + SA_BYTES;

        #pragma unroll
        for (int ks = 0; ks < CHUNK_K / 16; ks++) {
            const uint32_t kbase = (uint32_t)ks * 32;
            uint32_t bbf[2][4];
            #pragma unroll
            for (int nb = 0; nb < 2; nb++) {
                uint32_t addr = Bs_u + (n0 + nb * 16 + b_row) * CROW_BYTES + kbase + b_kof * 2;
                ldsm_x4(bbf[nb], addr);
            }
            #pragma unroll
            for (int mi = 0; mi < 4; mi++) {
                uint32_t aa[4];
                uint32_t addr = As_u + (m0 + mi * 16 + a_row) * CROW_BYTES + kbase + a_kof * 2;
                ldsm_x4(aa, addr);
                #pragma unroll
                for (int ni = 0; ni < 4; ni++) {
                    int nb = ni >> 1, hi = ni & 1;
                    mma_16816_bf16(acc[mi][ni], aa, bbf[nb][hi * 2], bbf[nb][hi * 2 + 1]);
                }
            }
        }
    }
    __syncthreads();   // all MMAs done before smem is reused as transpose buffer

    // ---- epilogue: e = exp(-(sqi+sqj-2g)/2s^2); direct store; keep e in acc --
    const float inv = g_inv;
    #pragma unroll
    for (int mi = 0; mi < 4; mi++) {
        const int rl0 = m0 + mi * 16 + (lane >> 2);
        const int gi  = row0 + rl0;
        const float sqi0 = g_sq[gi];
        const float sqi8 = g_sq[gi + 8];
        #pragma unroll
        for (int ni = 0; ni < 4; ni++) {
            const int cl = n0 + ni * 8 + ((lane & 3) << 1);
            const int gj = col0 + cl;
            const float2 sj = *reinterpret_cast<const float2*>(&g_sq[gj]);
            float e0 = __expf(-fmaxf(sqi0 + sj.x - 2.f * acc[mi][ni][0], 0.f) * inv);
            float e1 = __expf(-fmaxf(sqi0 + sj.y - 2.f * acc[mi][ni][1], 0.f) * inv);
            float e2 = __expf(-fmaxf(sqi8 + sj.x - 2.f * acc[mi][ni][2], 0.f) * inv);
            float e3 = __expf(-fmaxf(sqi8 + sj.y - 2.f * acc[mi][ni][3], 0.f) * inv);
            *reinterpret_cast<float2*>(&d_out[(size_t)gi * N_DIM + gj])       = make_float2(e0, e1);
            *reinterpret_cast<float2*>(&d_out[(size_t)(gi + 8) * N_DIM + gj]) = make_float2(e2, e3);
            acc[mi][ni][0] = e0; acc[mi][ni][1] = e1;
            acc[mi][ni][2] = e2; acc[mi][ni][3] = e3;
        }
    }

    // ---- mirror store in two 128-row phases through smem transpose buffer ----
    if (mirror) {
        float* trans = reinterpret_cast<float*>(smem);
        #pragma unroll
        for (int p = 0; p < 2; p++) {
            if ((warp_m >> 1) == p) {
                const int rh_base = (warp_m & 1) * 64 + (lane >> 2);
                #pragma unroll
                for (int mi = 0; mi < 4; mi++) {
                    const int rh = rh_base + mi * 16;
                    #pragma unroll
                    for (int ni = 0; ni < 4; ni++) {
                        const int cl = n0 + ni * 8 + ((lane & 3) << 1);
                        trans[(cl)     * T_ST + rh]     = acc[mi][ni][0];
                        trans[(cl + 1) * T_ST + rh]     = acc[mi][ni][1];
                        trans[(cl)     * T_ST + rh + 8] = acc[mi][ni][2];
                        trans[(cl + 1) * T_ST + rh + 8] = acc[mi][ni][3];
                    }
                }
            }
            __syncthreads();
            #pragma unroll
            for (int it = 0; it < 8; it++) {
                int e4 = tid + it * NTHREADS;
                int r  = e4 >> 5;
                int c4 = e4 & 31;
                const float* src = &trans[r * T_ST + c4 * 4];
                float4 v = make_float4(src[0], src[1], src[2], src[3]);
                *reinterpret_cast<float4*>(
                    &d_out[(size_t)(col0 + r) * N_DIM + row0 + p * 128 + c4 * 4]) = v;
            }
            __syncthreads();
        }
    }
}

// ---------------- launcher ----------------
extern "C" void kernel_launch(void* const* d_in, const int* in_sizes, int n_in,
                              void* d_out, int out_size) {
    const float* x = (const float*)d_in[0];
    float* out = (float*)d_out;

    static bool attr_set = false;
    if (!attr_set) {
        cudaFuncSetAttribute(gemm_fused_kernel,
                             cudaFuncAttributeMaxDynamicSharedMemorySize, GEMM_SMEM);
        attr_set = true;
    }

    prep_kernel<<<1024, 256>>>(x);
    sigma_a_kernel<<<64, 256>>>();
    sigma_b_kernel<<<1, 256>>>();
    gemm_fused_kernel<<<NUM_CTAS, NTHREADS, GEMM_SMEM>>>(out);
}

// round 15
// speedup vs baseline: 1.2522x; 1.0415x over previous
#include <cuda_runtime.h>
#include <cuda_bf16.h>
#include <cstdint>

#define N_DIM 4096
#define D_DIM 256
#define TILE  128
#define GRID_TILES (N_DIM / TILE)       // 32
#define NUM_CTAS   (GRID_TILES * (GRID_TILES + 1) / 2)  // 528 upper-tri tiles

// ---------------- device scratch ----------------
__device__ __nv_bfloat16 g_xb[N_DIM * D_DIM];     // 2 MB bf16 copy of x
__device__ float g_sq[N_DIM];                      // row squared norms
__device__ float g_svec_partial[1024][D_DIM];      // colsum partials (1 MB)
__device__ float g_svec2[64][D_DIM];               // stage-2 colsum partials
__device__ float g_sqp[64];                        // stage-2 row-norm partials
__device__ float g_inv;                            // 1 / (2 * sigma^2)

// ---------------- helpers ----------------
__device__ __forceinline__ uint32_t smem_to_u32(const void* p) {
    uint32_t a;
    asm("{ .reg .u64 t; cvta.to.shared.u64 t, %1; cvt.u32.u64 %0, t; }" : "=r"(a) : "l"(p));
    return a;
}

__device__ __forceinline__ void ldsm_x4(uint32_t r[4], uint32_t addr) {
    asm volatile("ldmatrix.sync.aligned.m8n8.x4.shared.b16 {%0,%1,%2,%3}, [%4];"
                 : "=r"(r[0]), "=r"(r[1]), "=r"(r[2]), "=r"(r[3]) : "r"(addr));
}

__device__ __forceinline__ void mma_16816_bf16(float c[4], const uint32_t a[4],
                                               uint32_t b0, uint32_t b1) {
    asm volatile(
        "mma.sync.aligned.m16n8k16.row.col.f32.bf16.bf16.f32 "
        "{%0,%1,%2,%3}, {%4,%5,%6,%7}, {%8,%9}, {%0,%1,%2,%3};"
        : "+f"(c[0]), "+f"(c[1]), "+f"(c[2]), "+f"(c[3])
        : "r"(a[0]), "r"(a[1]), "r"(a[2]), "r"(a[3]), "r"(b0), "r"(b1));
}

#define CP_ASYNC_16(dst, src) \
    asm volatile("cp.async.cg.shared.global [%0], [%1], 16;" :: "r"(dst), "l"(src))
#define CP_ASYNC_COMMIT() asm volatile("cp.async.commit_group;" ::: "memory")
#define CP_ASYNC_WAIT(n)  asm volatile("cp.async.wait_group %0;" :: "n"(n) : "memory")

// ---------------- kernel 1: bf16 convert + row norms + colsum (single pass) ---
// 1024 blocks x 256 threads; block handles 4 rows; colsum folded via smem (no
// second read of x).
__global__ void prep_kernel(const float* __restrict__ x) {
    __shared__ float sh_half[8];
    __shared__ float sh_col[4][256];
    const int tid  = threadIdx.x;
    const int lane = tid & 31;
    const int r    = tid >> 6;             // local row 0..3
    const int c    = tid & 63;             // float4 index within row
    const int row  = blockIdx.x * 4 + r;

    float4 v = reinterpret_cast<const float4*>(x)[(size_t)row * 64 + c];
    float s = v.x * v.x + v.y * v.y + v.z * v.z + v.w * v.w;
    __nv_bfloat162 lo = __float22bfloat162_rn(make_float2(v.x, v.y));
    __nv_bfloat162 hi = __float22bfloat162_rn(make_float2(v.z, v.w));
    reinterpret_cast<uint2*>(g_xb)[(size_t)row * 64 + c] =
        make_uint2(*reinterpret_cast<uint32_t*>(&lo),
                   *reinterpret_cast<uint32_t*>(&hi));
    *reinterpret_cast<float4*>(&sh_col[r][c * 4]) = v;

    #pragma unroll
    for (int o = 16; o; o >>= 1) s += __shfl_xor_sync(0xffffffffu, s, o);
    if (lane == 0) sh_half[tid >> 5] = s;
    __syncthreads();

    if (tid < 4) g_sq[blockIdx.x * 4 + tid] = sh_half[2 * tid] + sh_half[2 * tid + 1];
    // colsum over the block's 4 rows (deterministic fixed order)
    float acc = sh_col[0][tid] + sh_col[1][tid] + sh_col[2][tid] + sh_col[3][tid];
    g_svec_partial[blockIdx.x][tid] = acc;
}

// ---------------- kernel 2a: parallel fold 1024 -> 64 partial rows ------------
__global__ void sigma_a_kernel() {
    const int b = blockIdx.x;    // 64 blocks
    const int t = threadIdx.x;   // 256 threads
    float s = 0.f;
    #pragma unroll
    for (int r = 0; r < 16; r++) s += g_svec_partial[b * 16 + r][t];
    g_svec2[b][t] = s;

    __shared__ float sh[64];
    if (t < 64) sh[t] = g_sq[b * 64 + t];
    __syncthreads();
    if (t < 32) {
        float v = sh[t] + sh[t + 32];
        #pragma unroll
        for (int o = 16; o; o >>= 1) v += __shfl_xor_sync(0xffffffffu, v, o);
        if (t == 0) g_sqp[b] = v;
    }
}

// ---------------- kernel 2b: final sigma -> g_inv -----------------------------
__global__ void sigma_b_kernel() {
    const int t = threadIdx.x;   // 256 threads
    float sc = 0.f;
    #pragma unroll
    for (int r = 0; r < 64; r++) sc += g_svec2[r][t];
    __shared__ double sh_ss[256], sh_sq[256];
    sh_ss[t] = (double)sc * (double)sc;
    sh_sq[t] = (t < 64) ? (double)g_sqp[t] : 0.0;
    __syncthreads();
    for (int o = 128; o; o >>= 1) {
        if (t < o) { sh_ss[t] += sh_ss[t + o]; sh_sq[t] += sh_sq[t + o]; }
        __syncthreads();
    }
    if (t == 0) {
        const double N = (double)N_DIM;
        double mean_d2 = 2.0 * sh_sq[0] / N - 2.0 * sh_ss[0] / (N * N);
        g_inv = (float)(1.0 / (2.0 * mean_d2));  // ALPHA = 1
    }
}

// ---------------- kernel 3: fused symmetric GEMM + d2 + exp (occupancy 2) -----
// CTA tile 128x128, 256 threads, 4x2 warps (warp tile 32x64). K in 4 chunks of
// 64, 3-stage cp.async pipeline (110.6 KB smem/CTA -> 2 CTAs per SM). One CTA's
// epilogue/barriers overlap the other's MMAs.
#define NTHREADS   256
#define CHUNK_K    64
#define NCHUNK     (D_DIM / CHUNK_K)     // 4
#define NSTAGE     3
#define CROW_BYTES 144
#define SA_BYTES   (TILE * CROW_BYTES)            // 18432
#define STAGE_BYTES (2 * SA_BYTES)                // 36864
#define GEMM_SMEM  (NSTAGE * STAGE_BYTES)         // 110592
#define T_ST 132

__global__ __launch_bounds__(NTHREADS, 2)
void gemm_fused_kernel(float* __restrict__ d_out) {
    extern __shared__ char smem[];
    const uint32_t smem_u = smem_to_u32(smem);

    const int tid  = threadIdx.x;
    const int wid  = tid >> 5;
    const int lane = tid & 31;

    // decode upper-triangular tile (ti, tj), row ti has 32-ti tiles
    int b = blockIdx.x, ti = 0, rem = GRID_TILES;
    while (b >= rem) { b -= rem; rem--; ti++; }
    const int tj = ti + b;
    const bool mirror = (ti != tj);
    const int row0 = ti * TILE;
    const int col0 = tj * TILE;

    const __nv_bfloat16* gA = g_xb + (size_t)row0 * D_DIM;
    const __nv_bfloat16* gB = g_xb + (size_t)col0 * D_DIM;

    auto load_chunk = [&](int c, int stage) {
        const uint32_t sA = smem_u + stage * STAGE_BYTES;
        const uint32_t sB = sA + SA_BYTES;
        #pragma unroll
        for (int it = 0; it < 4; it++) {
            int idx = tid + it * NTHREADS;
            int r = idx >> 3, q = idx & 7;
            uint32_t soff = (uint32_t)r * CROW_BYTES + (uint32_t)q * 16;
            size_t goff = (size_t)r * D_DIM + c * CHUNK_K + q * 8;
            CP_ASYNC_16(sA + soff, gA + goff);
            CP_ASYNC_16(sB + soff, gB + goff);
        }
        CP_ASYNC_COMMIT();
    };

    // 4 warps along M (32 rows each), 2 along N (64 cols each)
    const int warp_m = wid & 3;
    const int warp_n = wid >> 2;
    const int m0 = warp_m * 32;
    const int n0 = warp_n * 64;

    float acc[2][8][4];
    #pragma unroll
    for (int mi = 0; mi < 2; mi++)
        #pragma unroll
        for (int ni = 0; ni < 8; ni++)
            #pragma unroll
            for (int q = 0; q < 4; q++) acc[mi][ni][q] = 0.f;

    const uint32_t a_row = (uint32_t)(lane & 15);
    const uint32_t a_kof = (uint32_t)((lane >> 4) << 3);
    const uint32_t b_row = (uint32_t)(((lane >> 4) << 3) + (lane & 7));
    const uint32_t b_kof = (uint32_t)(((lane >> 3) & 1) << 3);

    load_chunk(0, 0);

    #pragma unroll
    for (int c = 0; c < NCHUNK; c++) {
        const int stage = c % NSTAGE;
        if (c + 1 < NCHUNK) { load_chunk(c + 1, (c + 1) % NSTAGE); CP_ASYNC_WAIT(1); }
        else                { CP_ASYNC_WAIT(0); }
        __syncthreads();

        const uint32_t As_u = smem_u + stage * STAGE_BYTES;
        const uint32_t Bs_u = As_u + SA_BYTES;

        #pragma unroll
        for (int ks = 0; ks < CHUNK_K / 16; ks++) {
            const uint32_t kbase = (uint32_t)ks * 32;
            uint32_t bbf[4][4];
            #pragma unroll
            for (int nb = 0; nb < 4; nb++) {
                uint32_t addr = Bs_u + (n0 + nb * 16 + b_row) * CROW_BYTES + kbase + b_kof * 2;
                ldsm_x4(bbf[nb], addr);
            }
            #pragma unroll
            for (int mi = 0; mi < 2; mi++) {
                uint32_t aa[4];
                uint32_t addr = As_u + (m0 + mi * 16 + a_row) * CROW_BYTES + kbase + a_kof * 2;
                ldsm_x4(aa, addr);
                #pragma unroll
                for (int ni = 0; ni < 8; ni++) {
                    int nb = ni >> 1, hi = ni & 1;
                    mma_16816_bf16(acc[mi][ni], aa, bbf[nb][hi * 2], bbf[nb][hi * 2 + 1]);
                }
            }
        }
    }
    __syncthreads();   // all MMAs done before smem is reused as transpose buffer

    // ---- epilogue: e = exp(-(sqi+sqj-2g)/2s^2); direct store; keep e in acc --
    const float inv = g_inv;
    #pragma unroll
    for (int mi = 0; mi < 2; mi++) {
        const int rl0 = m0 + mi * 16 + (lane >> 2);   // local row 0..127
        const int gi  = row0 + rl0;
        const float sqi0 = g_sq[gi];
        const float sqi8 = g_sq[gi + 8];
        #pragma unroll
        for (int ni = 0; ni < 8; ni++) {
            const int cl = n0 + ni * 8 + ((lane & 3) << 1);   // local col 0..127
            const int gj = col0 + cl;
            const float2 sj = *reinterpret_cast<const float2*>(&g_sq[gj]);
            float e0 = __expf(-fmaxf(sqi0 + sj.x - 2.f * acc[mi][ni][0], 0.f) * inv);
            float e1 = __expf(-fmaxf(sqi0 + sj.y - 2.f * acc[mi][ni][1], 0.f) * inv);
            float e2 = __expf(-fmaxf(sqi8 + sj.x - 2.f * acc[mi][ni][2], 0.f) * inv);
            float e3 = __expf(-fmaxf(sqi8 + sj.y - 2.f * acc[mi][ni][3], 0.f) * inv);
            *reinterpret_cast<float2*>(&d_out[(size_t)gi * N_DIM + gj])       = make_float2(e0, e1);
            *reinterpret_cast<float2*>(&d_out[(size_t)(gi + 8) * N_DIM + gj]) = make_float2(e2, e3);
            acc[mi][ni][0] = e0; acc[mi][ni][1] = e1;
            acc[mi][ni][2] = e2; acc[mi][ni][3] = e3;
        }
    }

    // ---- mirror store: single-phase smem transpose (67.6 KB <= 110.6 KB) -----
    if (mirror) {
        float* trans = reinterpret_cast<float*>(smem);
        #pragma unroll
        for (int mi = 0; mi < 2; mi++) {
            const int rl0 = m0 + mi * 16 + (lane >> 2);
            #pragma unroll
            for (int ni = 0; ni < 8; ni++) {
                const int cl = n0 + ni * 8 + ((lane & 3) << 1);
                trans[(cl)     * T_ST + rl0]     = acc[mi][ni][0];
                trans[(cl + 1) * T_ST + rl0]     = acc[mi][ni][1];
                trans[(cl)     * T_ST + rl0 + 8] = acc[mi][ni][2];
                trans[(cl + 1) * T_ST + rl0 + 8] = acc[mi][ni][3];
            }
        }
        __syncthreads();
        // coalesced: 128 rows (col0+r) x 128 cols (row0..row0+127)
        #pragma unroll
        for (int it = 0; it < 16; it++) {
            int e4 = tid + it * NTHREADS;   // 4096 float4
            int r  = e4 >> 5;
            int c4 = e4 & 31;
            const float* src = &trans[r * T_ST + c4 * 4];
            float4 v = make_float4(src[0], src[1], src[2], src[3]);
            *reinterpret_cast<float4*>(
                &d_out[(size_t)(col0 + r) * N_DIM + row0 + c4 * 4]) = v;
        }
    }
}

// ---------------- launcher ----------------
extern "C" void kernel_launch(void* const* d_in, const int* in_sizes, int n_in,
                              void* d_out, int out_size) {
    const float* x = (const float*)d_in[0];
    float* out = (float*)d_out;

    static bool attr_set = false;
    if (!attr_set) {
        cudaFuncSetAttribute(gemm_fused_kernel,
                             cudaFuncAttributeMaxDynamicSharedMemorySize, GEMM_SMEM);
        attr_set = true;
    }

    prep_kernel<<<1024, 256>>>(x);
    sigma_a_kernel<<<64, 256>>>();
    sigma_b_kernel<<<1, 256>>>();
    gemm_fused_kernel<<<NUM_CTAS, NTHREADS, GEMM_SMEM>>>(out);
}

// round 17
// speedup vs baseline: 1.3348x; 1.0659x over previous
#include <cuda_runtime.h>
#include <cuda_bf16.h>
#include <cstdint>

#define N_DIM 4096
#define D_DIM 256
#define TILE  128
#define GRID_TILES (N_DIM / TILE)       // 32
#define NUM_CTAS   (GRID_TILES * (GRID_TILES + 1) / 2)  // 528 upper-tri tiles

// ---------------- device scratch ----------------
__device__ __nv_bfloat16 g_xb[N_DIM * D_DIM];     // 2 MB bf16 copy of x
__device__ float g_sq[N_DIM];                      // row squared norms
__device__ float g_svec_partial[1024][D_DIM];      // colsum partials (1 MB)
__device__ float g_svec2[64][D_DIM];               // stage-2 colsum partials
__device__ float g_sqp[64];                        // stage-2 row-norm partials
__device__ float g_inv;                            // 1 / (2 * sigma^2)
__device__ int   g_cnt;                            // folder arrival counter
__device__ int   g_flag;                           // g_inv ready flag

// ---------------- helpers ----------------
__device__ __forceinline__ uint32_t smem_to_u32(const void* p) {
    uint32_t a;
    asm("{ .reg .u64 t; cvta.to.shared.u64 t, %1; cvt.u32.u64 %0, t; }" : "=r"(a) : "l"(p));
    return a;
}

__device__ __forceinline__ void ldsm_x4(uint32_t r[4], uint32_t addr) {
    asm volatile("ldmatrix.sync.aligned.m8n8.x4.shared.b16 {%0,%1,%2,%3}, [%4];"
                 : "=r"(r[0]), "=r"(r[1]), "=r"(r[2]), "=r"(r[3]) : "r"(addr));
}

__device__ __forceinline__ void mma_16816_bf16(float c[4], const uint32_t a[4],
                                               uint32_t b0, uint32_t b1) {
    asm volatile(
        "mma.sync.aligned.m16n8k16.row.col.f32.bf16.bf16.f32 "
        "{%0,%1,%2,%3}, {%4,%5,%6,%7}, {%8,%9}, {%0,%1,%2,%3};"
        : "+f"(c[0]), "+f"(c[1]), "+f"(c[2]), "+f"(c[3])
        : "r"(a[0]), "r"(a[1]), "r"(a[2]), "r"(a[3]), "r"(b0), "r"(b1));
}

#define CP_ASYNC_16(dst, src) \
    asm volatile("cp.async.cg.shared.global [%0], [%1], 16;" :: "r"(dst), "l"(src))
#define CP_ASYNC_COMMIT() asm volatile("cp.async.commit_group;" ::: "memory")
#define CP_ASYNC_WAIT(n)  asm volatile("cp.async.wait_group %0;" :: "n"(n) : "memory")

// ---------------- kernel 1: bf16 convert + row norms + colsum (single pass) ---
__global__ void prep_kernel(const float* __restrict__ x) {
    __shared__ float sh_half[8];
    __shared__ float sh_col[4][256];
    const int tid  = threadIdx.x;
    const int lane = tid & 31;
    const int r    = tid >> 6;             // local row 0..3
    const int c    = tid & 63;             // float4 index within row
    const int row  = blockIdx.x * 4 + r;

    if (blockIdx.x == 0 && tid == 0) { g_cnt = 0; g_flag = 0; }  // replay reset

    float4 v = reinterpret_cast<const float4*>(x)[(size_t)row * 64 + c];
    float s = v.x * v.x + v.y * v.y + v.z * v.z + v.w * v.w;
    __nv_bfloat162 lo = __float22bfloat162_rn(make_float2(v.x, v.y));
    __nv_bfloat162 hi = __float22bfloat162_rn(make_float2(v.z, v.w));
    reinterpret_cast<uint2*>(g_xb)[(size_t)row * 64 + c] =
        make_uint2(*reinterpret_cast<uint32_t*>(&lo),
                   *reinterpret_cast<uint32_t*>(&hi));
    *reinterpret_cast<float4*>(&sh_col[r][c * 4]) = v;

    #pragma unroll
    for (int o = 16; o; o >>= 1) s += __shfl_xor_sync(0xffffffffu, s, o);
    if (lane == 0) sh_half[tid >> 5] = s;
    __syncthreads();

    if (tid < 4) g_sq[blockIdx.x * 4 + tid] = sh_half[2 * tid] + sh_half[2 * tid + 1];
    float acc = sh_col[0][tid] + sh_col[1][tid] + sh_col[2][tid] + sh_col[3][tid];
    g_svec_partial[blockIdx.x][tid] = acc;
}

// ---------------- kernel 2: fused symmetric GEMM + d2 + exp + embedded sigma --
// CTA tile 128x128, 256 threads, 4x2 warps (warp tile 32x64). K in 4 chunks of
// 64, 3-stage cp.async pipeline (110.6 KB smem/CTA -> 2 CTAs per SM).
// CTAs 0-63 fold the colsum partials; CTA 0 finalizes 1/(2 sigma^2) and
// publishes it via flag; every CTA polls the flag only at epilogue entry.
#define NTHREADS   256
#define CHUNK_K    64
#define NCHUNK     (D_DIM / CHUNK_K)     // 4
#define NSTAGE     3
#define CROW_BYTES 144
#define SA_BYTES   (TILE * CROW_BYTES)            // 18432
#define STAGE_BYTES (2 * SA_BYTES)                // 36864
#define GEMM_SMEM  (NSTAGE * STAGE_BYTES)         // 110592
#define T_ST 132

__global__ __launch_bounds__(NTHREADS, 2)
void gemm_fused_kernel(float* __restrict__ d_out) {
    extern __shared__ char smem[];
    const uint32_t smem_u = smem_to_u32(smem);

    const int tid  = threadIdx.x;
    const int wid  = tid >> 5;
    const int lane = tid & 31;

    // ---- embedded sigma: folder CTAs 0..63 ----
    if (blockIdx.x < 64) {
        const int fb = blockIdx.x;
        float s = 0.f;
        #pragma unroll
        for (int r = 0; r < 16; r++) s += g_svec_partial[fb * 16 + r][tid];
        g_svec2[fb][tid] = s;
        float* shq = reinterpret_cast<float*>(smem);
        if (tid < 64) shq[tid] = g_sq[fb * 64 + tid];
        __syncthreads();
        if (tid < 32) {
            float v = shq[tid] + shq[tid + 32];
            #pragma unroll
            for (int o = 16; o; o >>= 1) v += __shfl_xor_sync(0xffffffffu, v, o);
            if (tid == 0) g_sqp[fb] = v;
        }
        __syncthreads();
        __threadfence();              // make this CTA's g_svec2/g_sqp visible
        __syncthreads();
        if (tid == 0) atomicAdd(&g_cnt, 1);
    }
    // ---- CTA 0 finalizes sigma ----
    if (blockIdx.x == 0) {
        if (tid == 0) { while (atomicAdd(&g_cnt, 0) < 64) __nanosleep(32); }
        __syncthreads();
        __threadfence();
        float sc = 0.f;
        #pragma unroll
        for (int r = 0; r < 64; r++) sc += g_svec2[r][tid];
        double* sh_ss = reinterpret_cast<double*>(smem);          // 2 KB
        double* sh_sq = reinterpret_cast<double*>(smem + 2048);   // 2 KB
        sh_ss[tid] = (double)sc * (double)sc;
        sh_sq[tid] = (tid < 64) ? (double)g_sqp[tid] : 0.0;
        __syncthreads();
        for (int o = 128; o; o >>= 1) {
            if (tid < o) { sh_ss[tid] += sh_ss[tid + o]; sh_sq[tid] += sh_sq[tid + o]; }
            __syncthreads();
        }
        if (tid == 0) {
            const double N = (double)N_DIM;
            double mean_d2 = 2.0 * sh_sq[0] / N - 2.0 * sh_ss[0] / (N * N);
            g_inv = (float)(1.0 / (2.0 * mean_d2));  // ALPHA = 1
            __threadfence();
            atomicExch(&g_flag, 1);
        }
    }
    __syncthreads();   // scratch smem free before pipeline stage 0

    // decode upper-triangular tile (ti, tj), row ti has 32-ti tiles
    int b = blockIdx.x, ti = 0, rem = GRID_TILES;
    while (b >= rem) { b -= rem; rem--; ti++; }
    const int tj = ti + b;
    const bool mirror = (ti != tj);
    const int row0 = ti * TILE;
    const int col0 = tj * TILE;

    const __nv_bfloat16* gA = g_xb + (size_t)row0 * D_DIM;
    const __nv_bfloat16* gB = g_xb + (size_t)col0 * D_DIM;

    auto load_chunk = [&](int c, int stage) {
        const uint32_t sA = smem_u + stage * STAGE_BYTES;
        const uint32_t sB = sA + SA_BYTES;
        #pragma unroll
        for (int it = 0; it < 4; it++) {
            int idx = tid + it * NTHREADS;
            int r = idx >> 3, q = idx & 7;
            uint32_t soff = (uint32_t)r * CROW_BYTES + (uint32_t)q * 16;
            size_t goff = (size_t)r * D_DIM + c * CHUNK_K + q * 8;
            CP_ASYNC_16(sA + soff, gA + goff);
            CP_ASYNC_16(sB + soff, gB + goff);
        }
        CP_ASYNC_COMMIT();
    };

    // 4 warps along M (32 rows each), 2 along N (64 cols each)
    const int warp_m = wid & 3;
    const int warp_n = wid >> 2;
    const int m0 = warp_m * 32;
    const int n0 = warp_n * 64;

    float acc[2][8][4];
    #pragma unroll
    for (int mi = 0; mi < 2; mi++)
        #pragma unroll
        for (int ni = 0; ni < 8; ni++)
            #pragma unroll
            for (int q = 0; q < 4; q++) acc[mi][ni][q] = 0.f;

    const uint32_t a_row = (uint32_t)(lane & 15);
    const uint32_t a_kof = (uint32_t)((lane >> 4) << 3);
    const uint32_t b_row = (uint32_t)(((lane >> 4) << 3) + (lane & 7));
    const uint32_t b_kof = (uint32_t)(((lane >> 3) & 1) << 3);

    load_chunk(0, 0);

    #pragma unroll
    for (int c = 0; c < NCHUNK; c++) {
        const int stage = c % NSTAGE;
        if (c + 1 < NCHUNK) { load_chunk(c + 1, (c + 1) % NSTAGE); CP_ASYNC_WAIT(1); }
        else                { CP_ASYNC_WAIT(0); }
        __syncthreads();

        const uint32_t As_u = smem_u + stage * STAGE_BYTES;
        const uint32_t Bs_u = As_u + SA_BYTES;

        #pragma unroll
        for (int ks = 0; ks < CHUNK_K / 16; ks++) {
            const uint32_t kbase = (uint32_t)ks * 32;
            uint32_t bbf[4][4];
            #pragma unroll
            for (int nb = 0; nb < 4; nb++) {
                uint32_t addr = Bs_u + (n0 + nb * 16 + b_row) * CROW_BYTES + kbase + b_kof * 2;
                ldsm_x4(bbf[nb], addr);
            }
            #pragma unroll
            for (int mi = 0; mi < 2; mi++) {
                uint32_t aa[4];
                uint32_t addr = As_u + (m0 + mi * 16 + a_row) * CROW_BYTES + kbase + a_kof * 2;
                ldsm_x4(aa, addr);
                #pragma unroll
                for (int ni = 0; ni < 8; ni++) {
                    int nb = ni >> 1, hi = ni & 1;
                    mma_16816_bf16(acc[mi][ni], aa, bbf[nb][hi * 2], bbf[nb][hi * 2 + 1]);
                }
            }
        }
    }
    __syncthreads();   // all MMAs done before smem is reused as transpose buffer

    // ---- wait for g_inv (normally long since published) ----
    if (tid == 0) {
        while (atomicAdd(&g_flag, 0) == 0) __nanosleep(64);
        __threadfence();
    }
    __syncthreads();

    // ---- epilogue: e = exp(-(sqi+sqj-2g)/2s^2); direct store; keep e in acc --
    const float inv = g_inv;
    #pragma unroll
    for (int mi = 0; mi < 2; mi++) {
        const int rl0 = m0 + mi * 16 + (lane >> 2);   // local row 0..127
        const int gi  = row0 + rl0;
        const float sqi0 = g_sq[gi];
        const float sqi8 = g_sq[gi + 8];
        #pragma unroll
        for (int ni = 0; ni < 8; ni++) {
            const int cl = n0 + ni * 8 + ((lane & 3) << 1);   // local col 0..127
            const int gj = col0 + cl;
            const float2 sj = *reinterpret_cast<const float2*>(&g_sq[gj]);
            float e0 = __expf(-fmaxf(sqi0 + sj.x - 2.f * acc[mi][ni][0], 0.f) * inv);
            float e1 = __expf(-fmaxf(sqi0 + sj.y - 2.f * acc[mi][ni][1], 0.f) * inv);
            float e2 = __expf(-fmaxf(sqi8 + sj.x - 2.f * acc[mi][ni][2], 0.f) * inv);
            float e3 = __expf(-fmaxf(sqi8 + sj.y - 2.f * acc[mi][ni][3], 0.f) * inv);
            *reinterpret_cast<float2*>(&d_out[(size_t)gi * N_DIM + gj])       = make_float2(e0, e1);
            *reinterpret_cast<float2*>(&d_out[(size_t)(gi + 8) * N_DIM + gj]) = make_float2(e2, e3);
            acc[mi][ni][0] = e0; acc[mi][ni][1] = e1;
            acc[mi][ni][2] = e2; acc[mi][ni][3] = e3;
        }
    }

    // ---- mirror store: single-phase smem transpose ----
    if (mirror) {
        float* trans = reinterpret_cast<float*>(smem);
        #pragma unroll
        for (int mi = 0; mi < 2; mi++) {
            const int rl0 = m0 + mi * 16 + (lane >> 2);
            #pragma unroll
            for (int ni = 0; ni < 8; ni++) {
                const int cl = n0 + ni * 8 + ((lane & 3) << 1);
                trans[(cl)     * T_ST + rl0]     = acc[mi][ni][0];
                trans[(cl + 1) * T_ST + rl0]     = acc[mi][ni][1];
                trans[(cl)     * T_ST + rl0 + 8] = acc[mi][ni][2];
                trans[(cl + 1) * T_ST + rl0 + 8] = acc[mi][ni][3];
            }
        }
        __syncthreads();
        #pragma unroll
        for (int it = 0; it < 16; it++) {
            int e4 = tid + it * NTHREADS;   // 4096 float4
            int r  = e4 >> 5;
            int c4 = e4 & 31;
            const float* src = &trans[r * T_ST + c4 * 4];
            float4 v = make_float4(src[0], src[1], src[2], src[3]);
            *reinterpret_cast<float4*>(
                &d_out[(size_t)(col0 + r) * N_DIM + row0 + c4 * 4]) = v;
        }
    }
}

// ---------------- launcher ----------------
extern "C" void kernel_launch(void* const* d_in, const int* in_sizes, int n_in,
                              void* d_out, int out_size) {
    const float* x = (const float*)d_in[0];
    float* out = (float*)d_out;

    static bool attr_set = false;
    if (!attr_set) {
        cudaFuncSetAttribute(gemm_fused_kernel,
                             cudaFuncAttributeMaxDynamicSharedMemorySize, GEMM_SMEM);
        attr_set = true;
    }

    prep_kernel<<<1024, 256>>>(x);
    gemm_fused_kernel<<<NUM_CTAS, NTHREADS, GEMM_SMEM>>>(out);
}